// round 1
// baseline (speedup 1.0000x reference)
#include <cuda_runtime.h>
#include <cuda_bf16.h>
#include <cstdio>

// ---------------- problem constants ----------------
#define BATCH   128
#define DIM     384
#define RES     14
#define NPIX    196            // RES*RES
#define HEADS   8
#define KD      32             // KEY_DIM
#define DV      128            // D = ATTN_RATIO*KEY_DIM
#define DH      1024           // DV*HEADS
#define OCQKV   1536           // 2*HEADS*KD + DH
#define SCALE_ATTN 0.17677669529663687f  // 32^-0.5

// ---------------- device scratch (no allocs allowed) ----------------
__device__ float g_qkv [BATCH * OCQKV * NPIX];   // [b][oc][n]  oc: 0..255 q, 256..511 k, 512..1535 v
__device__ float g_vloc[BATCH * DH    * NPIX];   // [b][ch][n]
__device__ float g_xout[BATCH * DH    * NPIX];   // relu(out + vloc), [b][ch][n]
__device__ float g_wqkv[OCQKV * DIM];
__device__ float g_bqkv[OCQKV];
__device__ float g_wproj[DIM * DH];
__device__ float g_bproj[DIM];

// ---------------- fold BN (and attention scale) into weights ----------------
__global__ void fold_qkv_kernel(
    const float* __restrict__ q_w, const float* __restrict__ q_b,
    const float* __restrict__ q_s, const float* __restrict__ q_t,
    const float* __restrict__ k_w, const float* __restrict__ k_b,
    const float* __restrict__ k_s, const float* __restrict__ k_t,
    const float* __restrict__ v_w, const float* __restrict__ v_b,
    const float* __restrict__ v_s, const float* __restrict__ v_t)
{
    int idx = blockIdx.x * blockDim.x + threadIdx.x;
    if (idx >= OCQKV * DIM) return;
    int oc = idx / DIM;
    int c  = idx - oc * DIM;
    float w, s;
    if (oc < 256) {
        w = q_w[oc * DIM + c];  s = q_s[oc] * SCALE_ATTN;
        if (c == 0) g_bqkv[oc] = (q_b[oc] * q_s[oc] + q_t[oc]) * SCALE_ATTN;
    } else if (oc < 512) {
        int o = oc - 256;
        w = k_w[o * DIM + c];   s = k_s[o];
        if (c == 0) g_bqkv[oc] = k_b[o] * k_s[o] + k_t[o];
    } else {
        int o = oc - 512;
        w = v_w[o * DIM + c];   s = v_s[o];
        if (c == 0) g_bqkv[oc] = v_b[o] * v_s[o] + v_t[o];
    }
    g_wqkv[idx] = w * s;
}

__global__ void fold_proj_kernel(
    const float* __restrict__ p_w, const float* __restrict__ p_b,
    const float* __restrict__ p_s, const float* __restrict__ p_t)
{
    int idx = blockIdx.x * blockDim.x + threadIdx.x;
    if (idx >= DIM * DH) return;
    int oc = idx / DH;
    g_wproj[idx] = p_w[idx] * p_s[oc];
    if ((idx - oc * DH) == 0) g_bproj[oc] = p_b[oc] * p_s[oc] + p_t[oc];
}

// ---------------- tiled GEMM: Y[b][oc][n] = W[oc][:] @ X[b][:][n] + bias ----------------
// BM=128 oc rows per CTA, full 196 cols, BK=16.  224 threads; per-thread tile 8x14.
// MODE 0: X = x input, W/b = folded qkv, Y = g_qkv, K=DIM, OC=OCQKV
// MODE 1: X = g_xout,  W/b = folded proj, Y = d_out, K=DH,  OC=DIM
template<int MODE>
__global__ __launch_bounds__(224)
void gemm_kernel(const float* __restrict__ Xin, float* __restrict__ Yout)
{
    const int K  = (MODE == 0) ? DIM   : DH;
    const int OC = (MODE == 0) ? OCQKV : DIM;
    const float* __restrict__ W  = (MODE == 0) ? g_wqkv : g_wproj;
    const float* __restrict__ Bv = (MODE == 0) ? g_bqkv : g_bproj;

    const int b   = blockIdx.x;
    const int oc0 = blockIdx.y * 128;
    const float* Xb = ((MODE == 0) ? Xin : g_xout) + (size_t)b * K * NPIX;
    float*       Yb = ((MODE == 0) ? g_qkv : Yout) + (size_t)b * OC * NPIX;

    __shared__ float sW[16][129];   // [kk][row]  (padded)
    __shared__ float sX[16][197];   // [kk][n]    (padded)

    const int tid = threadIdx.x;
    const int tx  = tid % 14;       // col group: cols tx + 14*j
    const int ty  = tid / 14;       // 0..15 -> oc rows ty*8 .. ty*8+7

    float acc[8][14];
    #pragma unroll
    for (int i = 0; i < 8; ++i)
        #pragma unroll
        for (int j = 0; j < 14; ++j) acc[i][j] = 0.f;

    for (int k0 = 0; k0 < K; k0 += 16) {
        // load W tile (128 x 16), coalesced along k
        for (int e = tid; e < 128 * 16; e += 224) {
            int row = e >> 4, col = e & 15;
            sW[col][row] = W[(size_t)(oc0 + row) * K + k0 + col];
        }
        // load X tile (16 x 196) — contiguous block in global
        for (int e = tid; e < 16 * NPIX; e += 224) {
            int kk = e / NPIX, n = e - kk * NPIX;
            sX[kk][n] = Xb[(k0 + kk) * NPIX + n];
        }
        __syncthreads();
        #pragma unroll
        for (int kk = 0; kk < 16; ++kk) {
            float wr[8], xr[14];
            #pragma unroll
            for (int i = 0; i < 8; ++i) wr[i] = sW[kk][ty * 8 + i];
            #pragma unroll
            for (int j = 0; j < 14; ++j) xr[j] = sX[kk][tx + 14 * j];
            #pragma unroll
            for (int i = 0; i < 8; ++i)
                #pragma unroll
                for (int j = 0; j < 14; ++j) acc[i][j] += wr[i] * xr[j];
        }
        __syncthreads();
    }

    #pragma unroll
    for (int i = 0; i < 8; ++i) {
        int oc = oc0 + ty * 8 + i;
        float bb = Bv[oc];
        float* yr = Yb + (size_t)oc * NPIX + tx;
        #pragma unroll
        for (int j = 0; j < 14; ++j) yr[14 * j] = acc[i][j] + bb;
    }
}

// ---------------- depthwise 3x3 local-V branch (+BN) ----------------
__global__ void vloc_kernel(
    const float* __restrict__ vl_w, const float* __restrict__ vl_b,
    const float* __restrict__ vl_s, const float* __restrict__ vl_t)
{
    int idx = blockIdx.x * blockDim.x + threadIdx.x;
    if (idx >= BATCH * DH * NPIX) return;
    int n  = idx % NPIX;
    int ch = (idx / NPIX) % DH;
    int b  = idx / (DH * NPIX);
    int i = n / RES, j = n - i * RES;

    const float* src = g_qkv + (size_t)b * OCQKV * NPIX + (size_t)(512 + ch) * NPIX;
    const float* wk  = vl_w + ch * 9;
    float acc = 0.f;
    #pragma unroll
    for (int di = 0; di < 3; ++di) {
        int ii = i + di - 1;
        if (ii < 0 || ii >= RES) continue;
        #pragma unroll
        for (int dj = 0; dj < 3; ++dj) {
            int jj = j + dj - 1;
            if (jj < 0 || jj >= RES) continue;
            acc += src[ii * RES + jj] * wk[di * 3 + dj];
        }
    }
    g_vloc[idx] = (acc + vl_b[ch]) * vl_s[ch] + vl_t[ch];
}

// ---------------- fused attention per (batch, 14-query-row tile) ----------------
// smem: sS (8x14x196 logits/probs) + sKV staging (32x197) + sQ (8x14x32)
#define NT 14
#define S_ELEMS (NT * NPIX)                  // 2744 per head
#define SMEM_FLOATS (HEADS * S_ELEMS + 32 * 197 + HEADS * NT * KD)
#define SMEM_BYTES (SMEM_FLOATS * 4)

__global__ __launch_bounds__(256)
void attn_kernel(const float* __restrict__ th1_w, const float* __restrict__ th1_b,
                 const float* __restrict__ th2_w, const float* __restrict__ th2_b,
                 const float* __restrict__ bias_seg, const int* __restrict__ bias_idxs,
                 int n_off)
{
    extern __shared__ float smem[];
    float* sS  = smem;                               // [h][r][m]
    float* sKV = sS + HEADS * S_ELEMS;               // [32][197]
    float* sQ  = sKV + 32 * 197;                     // [h][r][c]

    const int tile = blockIdx.x;          // 0..13
    const int b    = blockIdx.y;          // 0..127
    const int nq0  = tile * NT;
    const int tid  = threadIdx.x;
    const size_t base  = (size_t)b * OCQKV * NPIX;
    const size_t vbase = base + (size_t)512 * NPIX;
    const size_t xob   = (size_t)b * DH * NPIX;

    // load Q tile (scale already folded into q weights)
    for (int e = tid; e < HEADS * NT * KD; e += 256) {
        int h = e / (NT * KD);
        int r = (e / KD) % NT;
        int c = e % KD;
        sQ[e] = g_qkv[base + (size_t)(h * KD + c) * NPIX + nq0 + r];
    }

    // ---- logits: S[h][r][m] = q.k + bias ----
    for (int h = 0; h < HEADS; ++h) {
        __syncthreads();
        for (int e = tid; e < KD * NPIX; e += 256) {
            int c = e / NPIX, m = e - c * NPIX;
            sKV[c * 197 + m] = g_qkv[base + (size_t)(256 + h * KD + c) * NPIX + m];
        }
        __syncthreads();
        for (int e = tid; e < S_ELEMS; e += 256) {
            int r = e / NPIX, m = e - r * NPIX;
            const float* qrow = sQ + (h * NT + r) * KD;
            const float* kcol = sKV + m;
            float acc = 0.f;
            #pragma unroll
            for (int c = 0; c < KD; ++c) acc += qrow[c] * kcol[c * 197];
            acc += bias_seg[h * n_off + bias_idxs[(nq0 + r) * NPIX + m]];
            sS[h * S_ELEMS + e] = acc;
        }
    }
    __syncthreads();

    // ---- talking-heads mix #1 (pre-softmax) ----
    for (int e = tid; e < S_ELEMS; e += 256) {
        float sv[HEADS];
        #pragma unroll
        for (int i = 0; i < HEADS; ++i) sv[i] = sS[i * S_ELEMS + e];
        #pragma unroll
        for (int o = 0; o < HEADS; ++o) {
            float a = th1_b[o];
            #pragma unroll
            for (int i = 0; i < HEADS; ++i) a += th1_w[o * HEADS + i] * sv[i];
            sS[o * S_ELEMS + e] = a;
        }
    }
    __syncthreads();

    // ---- softmax over m, per (h, r) row; warp w owns h=w ----
    {
        const int w = tid / 32, lane = tid % 32;   // w = head
        for (int r = 0; r < NT; ++r) {
            float* p = sS + w * S_ELEMS + r * NPIX;
            float mx = -1e30f;
            for (int m = lane; m < NPIX; m += 32) mx = fmaxf(mx, p[m]);
            #pragma unroll
            for (int off = 16; off; off >>= 1) mx = fmaxf(mx, __shfl_xor_sync(~0u, mx, off));
            float s = 0.f;
            for (int m = lane; m < NPIX; m += 32) { float ev = __expf(p[m] - mx); p[m] = ev; s += ev; }
            #pragma unroll
            for (int off = 16; off; off >>= 1) s += __shfl_xor_sync(~0u, s, off);
            float inv = 1.f / s;
            for (int m = lane; m < NPIX; m += 32) p[m] *= inv;
        }
    }
    __syncthreads();

    // ---- talking-heads mix #2 (post-softmax) ----
    for (int e = tid; e < S_ELEMS; e += 256) {
        float sv[HEADS];
        #pragma unroll
        for (int i = 0; i < HEADS; ++i) sv[i] = sS[i * S_ELEMS + e];
        #pragma unroll
        for (int o = 0; o < HEADS; ++o) {
            float a = th2_b[o];
            #pragma unroll
            for (int i = 0; i < HEADS; ++i) a += th2_w[o * HEADS + i] * sv[i];
            sS[o * S_ELEMS + e] = a;
        }
    }

    // ---- out = A @ V, fused + vloc + relu -> g_xout ----
    for (int h = 0; h < HEADS; ++h) {
        for (int dc = 0; dc < DV / 32; ++dc) {
            __syncthreads();
            for (int e = tid; e < 32 * NPIX; e += 256) {
                int dd = e / NPIX, m = e - dd * NPIX;
                sKV[dd * 197 + m] = g_qkv[vbase + (size_t)(h * DV + dc * 32 + dd) * NPIX + m];
            }
            __syncthreads();
            for (int e = tid; e < NT * 32; e += 256) {
                int dd = e & 31, r = e >> 5;
                const float* pr = sS + h * S_ELEMS + r * NPIX;
                const float* vv = sKV + dd * 197;
                float acc = 0.f;
                #pragma unroll 4
                for (int m = 0; m < NPIX; ++m) acc += pr[m] * vv[m];
                int ch = h * DV + dc * 32 + dd;
                size_t oi = xob + (size_t)ch * NPIX + nq0 + r;
                float val = acc + g_vloc[oi];
                g_xout[oi] = fmaxf(val, 0.f);
            }
        }
    }
}

// ---------------- host launch ----------------
extern "C" void kernel_launch(void* const* d_in, const int* in_sizes, int n_in,
                              void* d_out, int out_size)
{
    const float* x        = (const float*)d_in[0];
    const float* q_w      = (const float*)d_in[1];
    const float* q_b      = (const float*)d_in[2];
    const float* q_s      = (const float*)d_in[3];
    const float* q_t      = (const float*)d_in[4];
    const float* k_w      = (const float*)d_in[5];
    const float* k_b      = (const float*)d_in[6];
    const float* k_s      = (const float*)d_in[7];
    const float* k_t      = (const float*)d_in[8];
    const float* v_w      = (const float*)d_in[9];
    const float* v_b      = (const float*)d_in[10];
    const float* v_s      = (const float*)d_in[11];
    const float* v_t      = (const float*)d_in[12];
    const float* vl_w     = (const float*)d_in[13];
    const float* vl_b     = (const float*)d_in[14];
    const float* vl_s     = (const float*)d_in[15];
    const float* vl_t     = (const float*)d_in[16];
    const float* th1_w    = (const float*)d_in[17];
    const float* th1_b    = (const float*)d_in[18];
    const float* th2_w    = (const float*)d_in[19];
    const float* th2_b    = (const float*)d_in[20];
    const float* proj_w   = (const float*)d_in[21];
    const float* proj_b   = (const float*)d_in[22];
    const float* proj_s   = (const float*)d_in[23];
    const float* proj_t   = (const float*)d_in[24];
    const float* bias_seg = (const float*)d_in[25];
    const int*   bias_idx = (const int*)  d_in[26];
    float*       out      = (float*)d_out;

    const int n_off = in_sizes[25] / HEADS;

    cudaFuncSetAttribute(attn_kernel, cudaFuncAttributeMaxDynamicSharedMemorySize, SMEM_BYTES);

    // 1. fold BN into weights
    fold_qkv_kernel<<<(OCQKV * DIM + 255) / 256, 256>>>(q_w, q_b, q_s, q_t,
                                                        k_w, k_b, k_s, k_t,
                                                        v_w, v_b, v_s, v_t);
    fold_proj_kernel<<<(DIM * DH + 255) / 256, 256>>>(proj_w, proj_b, proj_s, proj_t);

    // 2. QKV projection GEMM -> g_qkv
    gemm_kernel<0><<<dim3(BATCH, OCQKV / 128), 224>>>(x, nullptr);

    // 3. depthwise local-V branch -> g_vloc
    vloc_kernel<<<(BATCH * DH * NPIX + 255) / 256, 256>>>(vl_w, vl_b, vl_s, vl_t);

    // 4. fused attention (+vloc +relu) -> g_xout
    attn_kernel<<<dim3(NPIX / NT, BATCH), 256, SMEM_BYTES>>>(th1_w, th1_b, th2_w, th2_b,
                                                             bias_seg, bias_idx, n_off);

    // 5. projection GEMM -> d_out
    gemm_kernel<1><<<dim3(BATCH, DIM / 128), 224>>>(nullptr, out);
}

// round 2
// speedup vs baseline: 3.4870x; 3.4870x over previous
#include <cuda_runtime.h>
#include <cstdint>

// ---------------- problem constants ----------------
#define BATCH   128
#define DIM     384
#define RES     14
#define NPIX    196
#define HEADS   8
#define KD      32
#define DV      128
#define DH      1024
#define OCQKV   1536
#define SCALE_ATTN 0.17677669529663687f
#define NPAD    208              // padded pixel dim: 26 tiles of 8
#define QT      16               // query rows per attention CTA
#define QTILES  13               // ceil(196/16)
#define SP      208              // S-matrix row stride in smem

// ---------------- device scratch ----------------
__device__ float g_qkv [(size_t)BATCH * OCQKV * NPIX];
__device__ float g_vloc[(size_t)BATCH * DH * NPIX];
__device__ float g_xout[(size_t)BATCH * DH * NPIX];
__device__ float g_wqkv[OCQKV * DIM];
__device__ float g_bqkv[OCQKV];
__device__ float g_wproj[DIM * DH];
__device__ float g_bproj[DIM];
__device__ float g_wvl[DH * 9];
__device__ float g_bvl[DH];
__device__ float g_bias[HEADS * NPIX * NPIX];

// ---------------- tf32 helpers ----------------
__device__ __forceinline__ uint32_t f2tf(float f) {
    uint32_t u; asm("cvt.rna.tf32.f32 %0, %1;" : "=r"(u) : "f"(f)); return u;
}
__device__ __forceinline__ void mma8(float* c, uint32_t a0, uint32_t a1, uint32_t a2, uint32_t a3,
                                     uint32_t b0, uint32_t b1) {
    asm volatile(
        "mma.sync.aligned.m16n8k8.row.col.f32.tf32.tf32.f32 "
        "{%0,%1,%2,%3},{%4,%5,%6,%7},{%8,%9},{%0,%1,%2,%3};"
        : "+f"(c[0]), "+f"(c[1]), "+f"(c[2]), "+f"(c[3])
        : "r"(a0), "r"(a1), "r"(a2), "r"(a3), "r"(b0), "r"(b1));
}

// ---------------- BN folding ----------------
__global__ void fold_qkv_kernel(
    const float* __restrict__ q_w, const float* __restrict__ q_b,
    const float* __restrict__ q_s, const float* __restrict__ q_t,
    const float* __restrict__ k_w, const float* __restrict__ k_b,
    const float* __restrict__ k_s, const float* __restrict__ k_t,
    const float* __restrict__ v_w, const float* __restrict__ v_b,
    const float* __restrict__ v_s, const float* __restrict__ v_t)
{
    int idx = blockIdx.x * blockDim.x + threadIdx.x;
    if (idx >= OCQKV * DIM) return;
    int oc = idx / DIM, c = idx - oc * DIM;
    float w, s;
    if (oc < 256) {
        w = q_w[oc * DIM + c]; s = q_s[oc] * SCALE_ATTN;
        if (c == 0) g_bqkv[oc] = (q_b[oc] * q_s[oc] + q_t[oc]) * SCALE_ATTN;
    } else if (oc < 512) {
        int o = oc - 256;
        w = k_w[o * DIM + c]; s = k_s[o];
        if (c == 0) g_bqkv[oc] = k_b[o] * k_s[o] + k_t[o];
    } else {
        int o = oc - 512;
        w = v_w[o * DIM + c]; s = v_s[o];
        if (c == 0) g_bqkv[oc] = v_b[o] * v_s[o] + v_t[o];
    }
    g_wqkv[idx] = w * s;
}

__global__ void fold_proj_kernel(
    const float* __restrict__ p_w, const float* __restrict__ p_b,
    const float* __restrict__ p_s, const float* __restrict__ p_t)
{
    int idx = blockIdx.x * blockDim.x + threadIdx.x;
    if (idx >= DIM * DH) return;
    int oc = idx / DH;
    g_wproj[idx] = p_w[idx] * p_s[oc];
    if ((idx - oc * DH) == 0) g_bproj[oc] = p_b[oc] * p_s[oc] + p_t[oc];
}

__global__ void fold_vl_kernel(
    const float* __restrict__ vl_w, const float* __restrict__ vl_b,
    const float* __restrict__ vl_s, const float* __restrict__ vl_t)
{
    int idx = blockIdx.x * blockDim.x + threadIdx.x;
    if (idx >= DH * 9) return;
    int ch = idx / 9;
    g_wvl[idx] = vl_w[idx] * vl_s[ch];
    if (idx == ch * 9) g_bvl[ch] = vl_b[ch] * vl_s[ch] + vl_t[ch];
}

__global__ void bias_expand_kernel(const float* __restrict__ bias_seg,
                                   const int* __restrict__ bias_idxs, int n_off)
{
    int e = blockIdx.x * blockDim.x + threadIdx.x;
    if (e >= HEADS * NPIX * NPIX) return;
    int h = e / (NPIX * NPIX), nm = e - h * (NPIX * NPIX);
    g_bias[e] = bias_seg[h * n_off + bias_idxs[nm]];
}

// ---------------- tf32 mma GEMM: Y[b][oc][n] = W @ X + bias ----------------
// CTA: 128 OC rows x 208 N cols (196 valid), 512 threads = 16 warps.
// warp w: oc-group (w>>1)*16, n-half (w&1) -> 13 n8 tiles.
#define BKG 32
template<int MODE>
__global__ __launch_bounds__(512, 1)
void gemm_mma(const float* __restrict__ Xin, float* __restrict__ Yout)
{
    const int K = (MODE == 0) ? DIM : DH;
    const float* __restrict__ W  = (MODE == 0) ? g_wqkv : g_wproj;
    const float* __restrict__ Bv = (MODE == 0) ? g_bqkv : g_bproj;
    const int b = blockIdx.x, oc0 = blockIdx.y * 128;
    const float* Xb = ((MODE == 0) ? Xin : g_xout) + (size_t)b * K * NPIX;
    float*       Yb = ((MODE == 0) ? g_qkv : Yout) + (size_t)b * ((MODE == 0) ? OCQKV : DIM) * NPIX;

    __shared__ uint32_t sW[BKG][129];   // tf32 [k][oc]
    __shared__ uint32_t sX[BKG][216];   // tf32 [k][n] (208 used, stride 216 = conflict-free)

    const int tid = threadIdx.x, lane = tid & 31, w = tid >> 5;
    const int ocg = w >> 1, half = w & 1, g = lane >> 2, q = lane & 3;
    const int ob = ocg * 16;

    float c[13][4];
    #pragma unroll
    for (int t = 0; t < 13; ++t) { c[t][0] = c[t][1] = c[t][2] = c[t][3] = 0.f; }

    for (int k0 = 0; k0 < K; k0 += BKG) {
        for (int e = tid; e < 128 * BKG; e += 512) {
            int oc = e >> 5, kk = e & 31;
            sW[kk][oc] = f2tf(W[(size_t)(oc0 + oc) * K + k0 + kk]);
        }
        for (int e = tid; e < BKG * NPAD; e += 512) {
            int kk = e / NPAD, n = e - kk * NPAD;
            sX[kk][n] = (n < NPIX) ? f2tf(Xb[(size_t)(k0 + kk) * NPIX + n]) : 0u;
        }
        __syncthreads();
        #pragma unroll
        for (int kk = 0; kk < 4; ++kk) {
            int cb = kk * 8;
            uint32_t a0 = sW[cb + q][ob + g],     a1 = sW[cb + q][ob + g + 8];
            uint32_t a2 = sW[cb + q + 4][ob + g], a3 = sW[cb + q + 4][ob + g + 8];
            #pragma unroll
            for (int t = 0; t < 13; ++t) {
                int n = (half * 13 + t) * 8 + g;
                mma8(c[t], a0, a1, a2, a3, sX[cb + q][n], sX[cb + q + 4][n]);
            }
        }
        __syncthreads();
    }

    int r1 = oc0 + ob + g, r2 = r1 + 8;
    float bb1 = Bv[r1], bb2 = Bv[r2];
    #pragma unroll
    for (int t = 0; t < 13; ++t) {
        int n0 = (half * 13 + t) * 8 + 2 * q;
        if (n0 < NPIX) {
            *(float2*)(Yb + (size_t)r1 * NPIX + n0) = make_float2(c[t][0] + bb1, c[t][1] + bb1);
            *(float2*)(Yb + (size_t)r2 * NPIX + n0) = make_float2(c[t][2] + bb2, c[t][3] + bb2);
        }
    }
}

// ---------------- depthwise 3x3 local-V (+folded BN), plane-per-block ----------------
__global__ __launch_bounds__(224)
void vloc_kernel()
{
    int blk = blockIdx.x;
    int b = blk >> 10, ch = blk & 1023;
    __shared__ float sp[NPIX];
    __shared__ float swv[9];
    int t = threadIdx.x;
    const float* src = g_qkv + (size_t)b * OCQKV * NPIX + (size_t)(512 + ch) * NPIX;
    if (t < NPIX) sp[t] = src[t];
    if (t < 9)  swv[t] = g_wvl[ch * 9 + t];
    __syncthreads();
    if (t < NPIX) {
        int i = t / RES, j = t - i * RES;
        float acc = g_bvl[ch];
        #pragma unroll
        for (int di = 0; di < 3; ++di) {
            int ii = i + di - 1;
            if (ii < 0 || ii >= RES) continue;
            #pragma unroll
            for (int dj = 0; dj < 3; ++dj) {
                int jj = j + dj - 1;
                if (jj < 0 || jj >= RES) continue;
                acc += sp[ii * RES + jj] * swv[di * 3 + dj];
            }
        }
        g_vloc[(size_t)b * DH * NPIX + (size_t)ch * NPIX + t] = acc;
    }
}

// ---------------- fused attention: mma QK^T, th-mix, softmax, th-mix, mma AV ----------------
// CTA per (query-tile, batch): 512 threads = 16 warps; warp w -> head (w>>1), half (w&1).
#define ATTN_SMEM (HEADS * QT * SP * 4)

__global__ __launch_bounds__(512, 1)
void attn_mma(const float* __restrict__ th1_w, const float* __restrict__ th1_b,
              const float* __restrict__ th2_w, const float* __restrict__ th2_b)
{
    extern __shared__ float sS[];            // [8][16][SP]
    __shared__ float sTh1[64], sTh1b[8], sTh2[64], sTh2b[8];

    const int tile = blockIdx.x, b = blockIdx.y;
    const int nq0 = tile * QT;
    const int tid = threadIdx.x, lane = tid & 31, w = tid >> 5;
    const int h = w >> 1, half = w & 1, g = lane >> 2, q = lane & 3;
    const size_t base = (size_t)b * OCQKV * NPIX;
    const size_t xob  = (size_t)b * DH * NPIX;

    if (tid < 64) { sTh1[tid] = th1_w[tid]; sTh2[tid] = th2_w[tid]; }
    if (tid < 8)  { sTh1b[tid] = th1_b[tid]; sTh2b[tid] = th2_b[tid]; }

    // ---- S = Q^T K (scale folded into Q), + bias, -> smem ----
    {
        const float* Qp = g_qkv + base + (size_t)(h * KD) * NPIX;
        const float* Kp = g_qkv + base + (size_t)(256 + h * KD) * NPIX;
        int ra = min(nq0 + g, NPIX - 1), rb = min(nq0 + g + 8, NPIX - 1);
        float c[13][4];
        #pragma unroll
        for (int t = 0; t < 13; ++t) { c[t][0] = c[t][1] = c[t][2] = c[t][3] = 0.f; }
        #pragma unroll
        for (int kk = 0; kk < 4; ++kk) {
            int cb = kk * 8;
            uint32_t a0 = f2tf(Qp[(cb + q) * NPIX + ra]);
            uint32_t a1 = f2tf(Qp[(cb + q) * NPIX + rb]);
            uint32_t a2 = f2tf(Qp[(cb + q + 4) * NPIX + ra]);
            uint32_t a3 = f2tf(Qp[(cb + q + 4) * NPIX + rb]);
            #pragma unroll
            for (int t = 0; t < 13; ++t) {
                int m = (half * 13 + t) * 8 + g;
                int mm = min(m, NPIX - 1);
                mma8(c[t], a0, a1, a2, a3,
                     f2tf(Kp[(cb + q) * NPIX + mm]), f2tf(Kp[(cb + q + 4) * NPIX + mm]));
            }
        }
        float* sh = sS + h * QT * SP;
        const float* bh = g_bias + h * NPIX * NPIX;
        #pragma unroll
        for (int t = 0; t < 13; ++t) {
            int m0 = (half * 13 + t) * 8 + 2 * q;
            int r1 = nq0 + g, r2 = nq0 + g + 8;
            float v0 = c[t][0], v1 = c[t][1], v2 = c[t][2], v3 = c[t][3];
            if (m0 < NPIX) {
                if (r1 < NPIX) { v0 += bh[r1 * NPIX + m0]; v1 += bh[r1 * NPIX + m0 + 1]; }
                if (r2 < NPIX) { v2 += bh[r2 * NPIX + m0]; v3 += bh[r2 * NPIX + m0 + 1]; }
            } else { v0 = v1 = v2 = v3 = 0.f; }
            sh[g * SP + m0]       = v0;  sh[g * SP + m0 + 1]       = v1;
            sh[(g + 8) * SP + m0] = v2;  sh[(g + 8) * SP + m0 + 1] = v3;
        }
    }
    __syncthreads();

    // ---- talking-heads mix #1 ----
    for (int e = tid; e < QT * NPIX; e += 512) {
        int r = e / NPIX, m = e - r * NPIX;
        float sv[8];
        #pragma unroll
        for (int i = 0; i < 8; ++i) sv[i] = sS[(i * QT + r) * SP + m];
        #pragma unroll
        for (int o = 0; o < 8; ++o) {
            float a = sTh1b[o];
            #pragma unroll
            for (int i = 0; i < 8; ++i) a += sTh1[o * 8 + i] * sv[i];
            sS[(o * QT + r) * SP + m] = a;
        }
    }
    __syncthreads();

    // ---- softmax: warp w owns head h, rows half*8 .. half*8+7 ----
    for (int rr = 0; rr < 8; ++rr) {
        float* p = sS + (h * QT + half * 8 + rr) * SP;
        float mx = -1e30f;
        for (int m = lane; m < NPIX; m += 32) mx = fmaxf(mx, p[m]);
        #pragma unroll
        for (int o = 16; o; o >>= 1) mx = fmaxf(mx, __shfl_xor_sync(~0u, mx, o));
        float s = 0.f;
        for (int m = lane; m < NPIX; m += 32) { float ev = __expf(p[m] - mx); p[m] = ev; s += ev; }
        #pragma unroll
        for (int o = 16; o; o >>= 1) s += __shfl_xor_sync(~0u, s, o);
        float inv = 1.f / s;
        for (int m = lane; m < NPIX; m += 32) p[m] *= inv;
    }
    __syncthreads();

    // ---- talking-heads mix #2 ----
    for (int e = tid; e < QT * NPIX; e += 512) {
        int r = e / NPIX, m = e - r * NPIX;
        float sv[8];
        #pragma unroll
        for (int i = 0; i < 8; ++i) sv[i] = sS[(i * QT + r) * SP + m];
        #pragma unroll
        for (int o = 0; o < 8; ++o) {
            float a = sTh2b[o];
            #pragma unroll
            for (int i = 0; i < 8; ++i) a += sTh2[o * 8 + i] * sv[i];
            sS[(o * QT + r) * SP + m] = a;
        }
    }
    __syncthreads();

    // ---- out = P @ V^T (mma over padded m; P padded cols are 0) ----
    {
        const float* Vp = g_qkv + base + (size_t)(512 + h * DV) * NPIX;
        const float* sP = sS + h * QT * SP;
        float c[8][4];
        #pragma unroll
        for (int t = 0; t < 8; ++t) { c[t][0] = c[t][1] = c[t][2] = c[t][3] = 0.f; }
        #pragma unroll
        for (int kk = 0; kk < 26; ++kk) {
            int mb = kk * 8;
            uint32_t a0 = f2tf(sP[g * SP + mb + q]);
            uint32_t a1 = f2tf(sP[(g + 8) * SP + mb + q]);
            uint32_t a2 = f2tf(sP[g * SP + mb + q + 4]);
            uint32_t a3 = f2tf(sP[(g + 8) * SP + mb + q + 4]);
            int m1 = min(mb + q, NPIX - 1), m2 = min(mb + q + 4, NPIX - 1);
            #pragma unroll
            for (int t = 0; t < 8; ++t) {
                int d = (half * 8 + t) * 8 + g;
                mma8(c[t], a0, a1, a2, a3,
                     f2tf(Vp[d * NPIX + m1]), f2tf(Vp[d * NPIX + m2]));
            }
        }
        __syncthreads();   // both warps of each head done reading P
        float* so = sS + h * QT * SP;   // reuse as out tile [d*17 + r]
        #pragma unroll
        for (int t = 0; t < 8; ++t) {
            int d = (half * 8 + t) * 8 + 2 * q;
            so[d * 17 + g]           = c[t][0];
            so[(d + 1) * 17 + g]     = c[t][1];
            so[d * 17 + g + 8]       = c[t][2];
            so[(d + 1) * 17 + g + 8] = c[t][3];
        }
    }
    __syncthreads();

    // ---- fused epilogue: + vloc, relu, coalesced store ----
    int rlim = min(QT, NPIX - nq0);
    for (int e = tid; e < HEADS * DV * QT; e += 512) {
        int h2 = e >> 11, rem = e & 2047, d = rem >> 4, r = rem & 15;
        if (r < rlim) {
            int ch = h2 * DV + d;
            size_t oi = xob + (size_t)ch * NPIX + nq0 + r;
            float val = sS[h2 * QT * SP + d * 17 + r] + g_vloc[oi];
            g_xout[oi] = fmaxf(val, 0.f);
        }
    }
}

// ---------------- host launch ----------------
extern "C" void kernel_launch(void* const* d_in, const int* in_sizes, int n_in,
                              void* d_out, int out_size)
{
    const float* x        = (const float*)d_in[0];
    const float* q_w      = (const float*)d_in[1];
    const float* q_b      = (const float*)d_in[2];
    const float* q_s      = (const float*)d_in[3];
    const float* q_t      = (const float*)d_in[4];
    const float* k_w      = (const float*)d_in[5];
    const float* k_b      = (const float*)d_in[6];
    const float* k_s      = (const float*)d_in[7];
    const float* k_t      = (const float*)d_in[8];
    const float* v_w      = (const float*)d_in[9];
    const float* v_b      = (const float*)d_in[10];
    const float* v_s      = (const float*)d_in[11];
    const float* v_t      = (const float*)d_in[12];
    const float* vl_w     = (const float*)d_in[13];
    const float* vl_b     = (const float*)d_in[14];
    const float* vl_s     = (const float*)d_in[15];
    const float* vl_t     = (const float*)d_in[16];
    const float* th1_w    = (const float*)d_in[17];
    const float* th1_b    = (const float*)d_in[18];
    const float* th2_w    = (const float*)d_in[19];
    const float* th2_b    = (const float*)d_in[20];
    const float* proj_w   = (const float*)d_in[21];
    const float* proj_b   = (const float*)d_in[22];
    const float* proj_s   = (const float*)d_in[23];
    const float* proj_t   = (const float*)d_in[24];
    const float* bias_seg = (const float*)d_in[25];
    const int*   bias_idx = (const int*)  d_in[26];
    float*       out      = (float*)d_out;

    const int n_off = in_sizes[25] / HEADS;

    cudaFuncSetAttribute(attn_mma, cudaFuncAttributeMaxDynamicSharedMemorySize, ATTN_SMEM);

    fold_qkv_kernel<<<(OCQKV * DIM + 255) / 256, 256>>>(q_w, q_b, q_s, q_t,
                                                        k_w, k_b, k_s, k_t,
                                                        v_w, v_b, v_s, v_t);
    fold_proj_kernel<<<(DIM * DH + 255) / 256, 256>>>(proj_w, proj_b, proj_s, proj_t);
    fold_vl_kernel<<<(DH * 9 + 255) / 256, 256>>>(vl_w, vl_b, vl_s, vl_t);
    bias_expand_kernel<<<(HEADS * NPIX * NPIX + 255) / 256, 256>>>(bias_seg, bias_idx, n_off);

    gemm_mma<0><<<dim3(BATCH, OCQKV / 128), 512>>>(x, nullptr);

    vloc_kernel<<<BATCH * DH, 224>>>();

    attn_mma<<<dim3(QTILES, BATCH), 512, ATTN_SMEM>>>(th1_w, th1_b, th2_w, th2_b);

    gemm_mma<1><<<dim3(BATCH, DIM / 128), 512>>>(nullptr, out);
}